// round 1
// baseline (speedup 1.0000x reference)
#include <cuda_runtime.h>
#include <cuda_bf16.h>

// Problem constants
#define BMAXR 32768
#define DDIM  1024
#define TTREE 8
#define NODES 63
#define LEAVES 64
#define NPAD  512      // TTREE * 64 (padded node/leaf count)
#define ODIM  128

// Scratch (static device globals -- no runtime allocation)
__device__ float g_s[(size_t)BMAXR * NPAD];    // smooth_step(logits), padded
__device__ float g_Wp[DDIM * NPAD];            // repacked node weights [d][t*64+i]
__device__ float g_LWp[NPAD * ODIM];           // repacked leaf weights [t*64+l][o]

// ---------------------------------------------------------------------------
// Repack kernels (tiny)
// ---------------------------------------------------------------------------
__global__ void repack_w(const float* __restrict__ nw) {
    int idx = blockIdx.x * blockDim.x + threadIdx.x;   // over DDIM*NPAD
    if (idx >= DDIM * NPAD) return;
    int d = idx / NPAD, c = idx % NPAD;
    int t = c >> 6, i = c & 63;
    float v = 0.0f;
    if (i < NODES) v = nw[((size_t)t * DDIM + d) * NODES + i];
    g_Wp[idx] = v;
}

__global__ void repack_lw(const float* __restrict__ lw) {
    int idx = blockIdx.x * blockDim.x + threadIdx.x;   // over NPAD*ODIM
    if (idx >= NPAD * ODIM) return;
    int c = idx / ODIM, o = idx % ODIM;
    int t = c >> 6, l = c & 63;
    g_LWp[idx] = lw[((size_t)t * ODIM + o) * LEAVES + l];
}

// ---------------------------------------------------------------------------
// smooth_step (matches reference: 0 for u<=-0.5, 1 for u>=0.5, else cubic)
// ---------------------------------------------------------------------------
__device__ __forceinline__ float smooth_step(float u) {
    if (u <= -0.5f) return 0.0f;
    if (u >= 0.5f)  return 1.0f;
    return -2.0f * u * u * u + 1.5f * u + 0.5f;
}

// ---------------------------------------------------------------------------
// K1: SGEMM [B x 1024] * [1024 x 512] with smooth_step epilogue -> g_s
// Tile 128x128x8, 256 threads, 8x8 microtile (split 4+4 in both dims)
// ---------------------------------------------------------------------------
#define BM 128
#define BN 128
#define BK 8

__global__ __launch_bounds__(256) void k1_gemm(const float* __restrict__ x) {
    __shared__ float As[BK][BM];
    __shared__ float Bs[BK][BN];

    const int bn = blockIdx.x;   // 0..3
    const int bm = blockIdx.y;   // 0..B/128-1
    const int tid = threadIdx.x;
    const int tx = tid & 15;     // 0..15
    const int ty = tid >> 4;     // 0..15

    const float* xg = x + (size_t)bm * BM * DDIM;
    const float* wg = g_Wp + bn * BN;

    // global load mapping
    const int arow = tid >> 1;          // 0..127
    const int acol = (tid & 1) * 4;     // 0 or 4
    const int brow = tid >> 5;          // 0..7
    const int bcol = (tid & 31) * 4;    // 0..124

    float acc[8][8];
    #pragma unroll
    for (int i = 0; i < 8; i++)
        #pragma unroll
        for (int j = 0; j < 8; j++) acc[i][j] = 0.0f;

    for (int k0 = 0; k0 < DDIM; k0 += BK) {
        float4 av = *(const float4*)(xg + (size_t)arow * DDIM + k0 + acol);
        float4 bv = *(const float4*)(wg + (size_t)(k0 + brow) * NPAD + bcol);
        As[acol + 0][arow] = av.x;
        As[acol + 1][arow] = av.y;
        As[acol + 2][arow] = av.z;
        As[acol + 3][arow] = av.w;
        *(float4*)&Bs[brow][bcol] = bv;
        __syncthreads();

        #pragma unroll
        for (int k = 0; k < BK; ++k) {
            float a[8], b[8];
            #pragma unroll
            for (int i = 0; i < 4; i++) {
                a[i]     = As[k][ty * 4 + i];
                a[4 + i] = As[k][64 + ty * 4 + i];
                b[i]     = Bs[k][tx * 4 + i];
                b[4 + i] = Bs[k][64 + tx * 4 + i];
            }
            #pragma unroll
            for (int i = 0; i < 8; i++)
                #pragma unroll
                for (int j = 0; j < 8; j++)
                    acc[i][j] = fmaf(a[i], b[j], acc[i][j]);
        }
        __syncthreads();
    }

    // epilogue: smooth_step + store to g_s
    #pragma unroll
    for (int hr = 0; hr < 2; hr++) {
        #pragma unroll
        for (int rr = 0; rr < 4; rr++) {
            int i = hr * 4 + rr;
            size_t row = (size_t)bm * BM + hr * 64 + ty * 4 + rr;
            float* srow = g_s + row * NPAD + bn * BN;
            float4 v0, v1;
            v0.x = smooth_step(acc[i][0]); v0.y = smooth_step(acc[i][1]);
            v0.z = smooth_step(acc[i][2]); v0.w = smooth_step(acc[i][3]);
            v1.x = smooth_step(acc[i][4]); v1.y = smooth_step(acc[i][5]);
            v1.z = smooth_step(acc[i][6]); v1.w = smooth_step(acc[i][7]);
            *(float4*)(srow + tx * 4)      = v0;
            *(float4*)(srow + 64 + tx * 4) = v1;
        }
    }
}

// ---------------------------------------------------------------------------
// K2: routing (mu) + leaf GEMM.  32 rows per block, 256 threads.
// Phase A: each thread owns (row, tree), builds 64 leaf probs fully unrolled.
// Phase B: [32 x 128] output tile, K=512, leaf weights streamed via smem.
// ---------------------------------------------------------------------------
#define K2_ROWS 32
#define MU_STRIDE 516   // 512 + pad (mult of 4 for float4, breaks bank aliasing)
#define K2_SMEM_BYTES ((K2_ROWS * MU_STRIDE + K2_ROWS * ODIM) * 4)

__global__ __launch_bounds__(256) void k2_route(float* __restrict__ out) {
    extern __shared__ float sh[];
    float* mu_s = sh;                            // [32][516]
    float* lw_s = sh + K2_ROWS * MU_STRIDE;      // [32][128]

    const int tid = threadIdx.x;
    const size_t bbase = (size_t)blockIdx.x * K2_ROWS;

    // ---------------- Phase A: routing probabilities ----------------
    {
        const int row  = tid & 31;   // lanes spread over rows -> fewer bank conflicts
        const int tree = tid >> 5;   // 0..7
        const float* srow = g_s + (bbase + row) * NPAD + tree * 64;

        float m[64];
        m[0] = 1.0f;
        int start = 0;
        #pragma unroll
        for (int lvl = 0; lvl < 6; ++lvl) {
            const int w = 1 << lvl;
            #pragma unroll
            for (int j = w - 1; j >= 0; --j) {      // descending: in-place safe
                float sv = srow[start + j];
                float p  = m[j];
                m[2 * j]     = p * sv;
                m[2 * j + 1] = p * (1.0f - sv);
            }
            start += w;
        }
        float* mrow = mu_s + row * MU_STRIDE + tree * 64;
        #pragma unroll
        for (int l = 0; l < 64; ++l) mrow[l] = m[l];
    }
    __syncthreads();

    // ---------------- Phase B: out[32][128] = mu[32][512] * LW[512][128] ----
    const int tx = tid & 31;     // col group: cols tx*4..+3
    const int ty = tid >> 5;     // row group: rows ty*4..+3

    float acc[4][4];
    #pragma unroll
    for (int r = 0; r < 4; r++)
        #pragma unroll
        for (int c = 0; c < 4; c++) acc[r][c] = 0.0f;

    for (int kk = 0; kk < NPAD; kk += 32) {
        // load LW chunk [32][128] cooperatively (coalesced float4)
        const float4* src = (const float4*)(g_LWp + (size_t)kk * ODIM);
        float4* dst = (float4*)lw_s;
        #pragma unroll
        for (int q = 0; q < 4; q++) dst[tid + 256 * q] = src[tid + 256 * q];
        __syncthreads();

        #pragma unroll 8
        for (int k = 0; k < 32; ++k) {
            float4 bv = *(const float4*)&lw_s[k * ODIM + tx * 4];
            #pragma unroll
            for (int r = 0; r < 4; r++) {
                float a = mu_s[(ty * 4 + r) * MU_STRIDE + kk + k];  // broadcast
                acc[r][0] = fmaf(a, bv.x, acc[r][0]);
                acc[r][1] = fmaf(a, bv.y, acc[r][1]);
                acc[r][2] = fmaf(a, bv.z, acc[r][2]);
                acc[r][3] = fmaf(a, bv.w, acc[r][3]);
            }
        }
        __syncthreads();
    }

    // store
    #pragma unroll
    for (int r = 0; r < 4; r++) {
        float4 v = make_float4(acc[r][0], acc[r][1], acc[r][2], acc[r][3]);
        *(float4*)(out + (bbase + ty * 4 + r) * ODIM + tx * 4) = v;
    }
}

// ---------------------------------------------------------------------------
// Launch
// ---------------------------------------------------------------------------
extern "C" void kernel_launch(void* const* d_in, const int* in_sizes, int n_in,
                              void* d_out, int out_size) {
    const float* x  = (const float*)d_in[0];   // [B, 1024]
    const float* nw = (const float*)d_in[1];   // [8, 1024, 63]
    const float* lw = (const float*)d_in[2];   // [8, 128, 64]
    float* out = (float*)d_out;                // [B, 128]

    int Brows = in_sizes[0] / DDIM;            // 32768

    cudaFuncSetAttribute(k2_route, cudaFuncAttributeMaxDynamicSharedMemorySize,
                         K2_SMEM_BYTES);

    repack_w <<< (DDIM * NPAD + 255) / 256, 256 >>> (nw);
    repack_lw<<< (NPAD * ODIM + 255) / 256, 256 >>> (lw);
    k1_gemm  <<< dim3(NPAD / BN, Brows / BM), 256 >>> (x);
    k2_route <<< Brows / K2_ROWS, 256, K2_SMEM_BYTES >>> (out);
}